// round 3
// baseline (speedup 1.0000x reference)
#include <cuda_runtime.h>
#include <cuda_bf16.h>

// Problem constants (fixed by dataset)
#define NMAX 100000
#define DIM  256      // IN = HID = OUT = 256
#define DIM2 512      // concat width
#define NEG_SLOPE 0.01f

// Scratch (device globals; no dynamic allocation allowed)
__device__ float BUF_A[(size_t)NMAX * DIM2]; // xcat / agg2 / xcat2   [N,512]
__device__ float BUF_B[(size_t)NMAX * DIM];  // h_lin / h2_lin        [N,256]
__device__ float BUF_C[(size_t)NMAX * DIM];  // agg1 / h1 (=f2)       [N,256]

__device__ __forceinline__ float leaky1(float v) {
    return v >= 0.0f ? v : NEG_SLOPE * v;
}
__device__ __forceinline__ float4 leaky4(float4 v) {
    v.x = leaky1(v.x); v.y = leaky1(v.y); v.z = leaky1(v.z); v.w = leaky1(v.w);
    return v;
}

// ---------------------------------------------------------------------------
// SGEMM: C[nrows,M] = A[nrows,K] @ B[K,M], optional bias + leaky epilogue.
// BM=BN=128, BK=16, 256 threads, 8x8 per thread (4+4 split rows/cols).
// ---------------------------------------------------------------------------
#define BM 128
#define BN 128
#define BK 16

__global__ void __launch_bounds__(256, 2) sgemm128(
    const float* __restrict__ A, const float* __restrict__ B,
    float* __restrict__ C, const float* __restrict__ bias,
    int nrows, int K, int M, int leakyFlag)
{
    __shared__ float As[BK][BM];
    __shared__ float Bs[BK][BN];

    const int tid  = threadIdx.x;
    const int row0 = blockIdx.x * BM;
    const int col0 = blockIdx.y * BN;

    const int trow = tid >> 4;    // 0..15
    const int tcol = tid & 15;    // 0..15

    const int arow = tid >> 2;        // 0..63
    const int acol = (tid & 3) * 4;   // 0,4,8,12
    const int brow = tid >> 5;        // 0..7
    const int bcol = (tid & 31) * 4;  // 0..124

    float acc[8][8];
    #pragma unroll
    for (int y = 0; y < 8; y++)
        #pragma unroll
        for (int x = 0; x < 8; x++) acc[y][x] = 0.0f;

    for (int k0 = 0; k0 < K; k0 += BK) {
        // A tile -> transposed into As[k][m]
        #pragma unroll
        for (int i = 0; i < 2; i++) {
            int r  = arow + 64 * i;
            int gr = row0 + r;
            float4 v = make_float4(0.f, 0.f, 0.f, 0.f);
            if (gr < nrows)
                v = *(const float4*)(A + (long long)gr * K + k0 + acol);
            As[acol + 0][r] = v.x;
            As[acol + 1][r] = v.y;
            As[acol + 2][r] = v.z;
            As[acol + 3][r] = v.w;
        }
        // B tile
        #pragma unroll
        for (int i = 0; i < 2; i++) {
            int r = brow + 8 * i;
            float4 v = *(const float4*)(B + (long long)(k0 + r) * M + col0 + bcol);
            *(float4*)(&Bs[r][bcol]) = v;
        }
        __syncthreads();

        #pragma unroll
        for (int k = 0; k < BK; k++) {
            float ra[8], rb[8];
            #pragma unroll
            for (int i = 0; i < 4; i++) {
                ra[i]     = As[k][trow * 4 + i];
                ra[i + 4] = As[k][64 + trow * 4 + i];
                rb[i]     = Bs[k][tcol * 4 + i];
                rb[i + 4] = Bs[k][64 + tcol * 4 + i];
            }
            #pragma unroll
            for (int y = 0; y < 8; y++)
                #pragma unroll
                for (int x = 0; x < 8; x++)
                    acc[y][x] += ra[y] * rb[x];
        }
        __syncthreads();
    }

    // epilogue + store (float4 along cols)
    #pragma unroll
    for (int y = 0; y < 8; y++) {
        int r  = trow * 4 + (y & 3) + (y >> 2) * 64;
        int gr = row0 + r;
        if (gr >= nrows) continue;
        #pragma unroll
        for (int xg = 0; xg < 2; xg++) {
            int c = col0 + tcol * 4 + xg * 64;
            float4 v;
            v.x = acc[y][xg * 4 + 0];
            v.y = acc[y][xg * 4 + 1];
            v.z = acc[y][xg * 4 + 2];
            v.w = acc[y][xg * 4 + 3];
            if (bias) {
                float4 bb = *(const float4*)(bias + c);
                v.x += bb.x; v.y += bb.y; v.z += bb.z; v.w += bb.w;
            }
            if (leakyFlag) v = leaky4(v);
            *(float4*)(C + (long long)gr * M + c) = v;
        }
    }
}

// ---------------------------------------------------------------------------
// Edge scatter: agg[dst] += w * h[src], one warp per edge, 256 cols.
// Indices are int32 (JAX demotes int64 without x64 mode).
// ---------------------------------------------------------------------------
__global__ void __launch_bounds__(256) scatter_kernel(
    const float* __restrict__ h,           // [N,256]
    float* __restrict__ agg,               // row stride ldagg
    const int* __restrict__ src,
    const int* __restrict__ dst,
    const float* __restrict__ w,
    int E, int ldagg)
{
    int warp = (blockIdx.x * blockDim.x + threadIdx.x) >> 5;
    int lane = threadIdx.x & 31;
    if (warp >= E) return;
    int s = src[warp];
    int d = dst[warp];
    float wt = w[warp];
    const float4* hrow = (const float4*)(h + (long long)s * DIM);
    float* arow = agg + (long long)d * ldagg;
    #pragma unroll
    for (int i = 0; i < 2; i++) {
        int g = lane + 32 * i;        // float4 group 0..63
        float4 v = hrow[g];
        int c = g * 4;
        atomicAdd(arow + c + 0, wt * v.x);
        atomicAdd(arow + c + 1, wt * v.y);
        atomicAdd(arow + c + 2, wt * v.z);
        atomicAdd(arow + c + 3, wt * v.w);
    }
}

// ---------------------------------------------------------------------------
// Zero helpers
// ---------------------------------------------------------------------------
__global__ void zero_kernel(float4* __restrict__ p, long long n4) {
    long long i = (long long)blockIdx.x * blockDim.x + threadIdx.x;
    if (i < n4) p[i] = make_float4(0.f, 0.f, 0.f, 0.f);
}

// zero first 256 columns of BUF_A rows (agg2 region)
__global__ void zero_Ahalf_kernel(int N) {
    int i = blockIdx.x;              // row
    int t = threadIdx.x;             // 0..63 float4 groups
    if (i >= N) return;
    ((float4*)(BUF_A + (long long)i * DIM2))[t] = make_float4(0.f, 0.f, 0.f, 0.f);
}

// ---------------------------------------------------------------------------
// build_xcat: h1 = agg1 + b1 (stored into BUF_C);
//   BUF_A[:, :256]   = leaky(h1)
//   BUF_A[:, 256:]   = leaky(features[root_idx[batch[i]]])
// ---------------------------------------------------------------------------
__global__ void __launch_bounds__(64) build_xcat_kernel(
    const float* __restrict__ features,
    const float* __restrict__ b1,
    const int* __restrict__ batch,
    const int* __restrict__ root_idx,
    int N)
{
    int i = blockIdx.x;
    int t = threadIdx.x;             // 0..63 (float4 per thread)
    if (i >= N) return;
    int rm = root_idx[batch[i]];

    float4 v  = ((float4*)(BUF_C + (long long)i * DIM))[t];
    float4 bb = ((const float4*)b1)[t];
    v.x += bb.x; v.y += bb.y; v.z += bb.z; v.w += bb.w;
    ((float4*)(BUF_C + (long long)i * DIM))[t] = v;                // h1 (=f2)
    ((float4*)(BUF_A + (long long)i * DIM2))[t] = leaky4(v);       // left half

    float4 f = ((const float4*)(features + (long long)rm * DIM))[t];
    ((float4*)(BUF_A + (long long)i * DIM2 + DIM))[t] = leaky4(f); // right half
}

// ---------------------------------------------------------------------------
// build_xcat2: BUF_A[:, :256] = leaky(agg2 + b2)  (in place)
//              BUF_A[:, 256:] = h1[root_idx[batch[i]]]   (raw, no leaky)
// ---------------------------------------------------------------------------
__global__ void __launch_bounds__(64) build_xcat2_kernel(
    const float* __restrict__ b2,
    const int* __restrict__ batch,
    const int* __restrict__ root_idx,
    int N)
{
    int i = blockIdx.x;
    int t = threadIdx.x;
    if (i >= N) return;
    int rm = root_idx[batch[i]];

    float4 v  = ((float4*)(BUF_A + (long long)i * DIM2))[t];
    float4 bb = ((const float4*)b2)[t];
    v.x += bb.x; v.y += bb.y; v.z += bb.z; v.w += bb.w;
    ((float4*)(BUF_A + (long long)i * DIM2))[t] = leaky4(v);

    float4 h1v = ((const float4*)(BUF_C + (long long)rm * DIM))[t];
    ((float4*)(BUF_A + (long long)i * DIM2 + DIM))[t] = h1v;
}

// ---------------------------------------------------------------------------
// launch
// ---------------------------------------------------------------------------
extern "C" void kernel_launch(void* const* d_in, const int* in_sizes, int n_in,
                              void* d_out, int out_size)
{
    const float* features = (const float*)d_in[0];       // [N,256]
    const float* values   = (const float*)d_in[1];       // [E]
    const float* W1       = (const float*)d_in[2];       // [256,256]
    const float* b1       = (const float*)d_in[3];       // [256]
    const float* W2       = (const float*)d_in[4];       // [512,256]
    const float* b2       = (const float*)d_in[5];       // [256]
    const float* Wl       = (const float*)d_in[6];       // [512,256]
    const float* bl       = (const float*)d_in[7];       // [256]
    const int*   adjs     = (const int*)d_in[8];         // [2,E] int32
    const int*   batch    = (const int*)d_in[9];         // [N]   int32
    const int*   root_idx = (const int*)d_in[10];        // [B]   int32
    float* out = (float*)d_out;

    const int N = in_sizes[0] / DIM;
    const int E = in_sizes[1];
    const int* src = adjs;
    const int* dst = adjs + E;

    // device-global symbol addresses (host-side pointers to the __device__ arrays)
    float *bufA, *bufB, *bufC;
    cudaGetSymbolAddress((void**)&bufA, BUF_A);
    cudaGetSymbolAddress((void**)&bufB, BUF_B);
    cudaGetSymbolAddress((void**)&bufC, BUF_C);

    dim3 gThreads(256);
    dim3 gGrid((N + BM - 1) / BM, DIM / BN);        // 782 x 2

    int scatterBlocks = (E + 7) / 8;                // 8 warps (edges) per block

    // 1. zero agg1 (BUF_C)
    {
        long long n4 = (long long)N * DIM / 4;
        int blocks = (int)((n4 + 255) / 256);
        zero_kernel<<<blocks, 256>>>((float4*)bufC, n4);
    }
    // 2. h_lin = features @ W1
    sgemm128<<<gGrid, gThreads>>>(features, W1, bufB, nullptr, N, DIM, DIM, 0);
    // 3. agg1[dst] += v * h_lin[src]
    scatter_kernel<<<scatterBlocks, 256>>>(bufB, bufC, src, dst, values, E, DIM);
    // 4. h1 = agg1 + b1; xcat = leaky([h1, features[root]])
    build_xcat_kernel<<<N, 64>>>(features, b1, batch, root_idx, N);
    // 5. h2_lin = xcat @ W2
    sgemm128<<<gGrid, gThreads>>>(bufA, W2, bufB, nullptr, N, DIM2, DIM, 0);
    // 6. zero agg2 region (BUF_A[:, :256])
    zero_Ahalf_kernel<<<N, 64>>>(N);
    // 7. agg2[dst] += v * h2_lin[src]
    scatter_kernel<<<scatterBlocks, 256>>>(bufB, bufA, src, dst, values, E, DIM2);
    // 8. xcat2 = [leaky(agg2 + b2), h1[root]]
    build_xcat2_kernel<<<N, 64>>>(b2, batch, root_idx, N);
    // 9. out = leaky(xcat2 @ Wl + bl)
    sgemm128<<<gGrid, gThreads>>>(bufA, Wl, out, bl, N, DIM2, DIM, 1);
}

// round 4
// speedup vs baseline: 1.9200x; 1.9200x over previous
#include <cuda_runtime.h>
#include <cuda_bf16.h>

#define NMAX 100000
#define DIM  256
#define NEG_SLOPE 0.01f

// -------------------- scratch (device globals) --------------------
__device__ float BUF_A[(size_t)NMAX * DIM];  // A2 / A3 (gemm inputs)
__device__ float BUF_B[(size_t)NMAX * DIM];  // h_lin / h2_lin (gemm outputs)
__device__ float BUF_C[(size_t)NMAX * DIM];  // agg1 / h1 / agg2
__device__ float WHI[5 * 65536];             // tf32-hi of W1, W2top, W2bot, Wltop, Wlbot
__device__ float WLO[5 * 65536];             // residual lo
__device__ float RA2[128 * DIM];             // leaky(features[root])
__device__ float RA3[128 * DIM];             // h1[root]
__device__ float RC2[128 * DIM];             // RA2 @ W2bot
__device__ float RC3[128 * DIM];             // RA3 @ Wlbot

__device__ __forceinline__ float leaky1(float v) { return v >= 0.0f ? v : NEG_SLOPE * v; }
__device__ __forceinline__ float4 leaky4(float4 v) {
    v.x = leaky1(v.x); v.y = leaky1(v.y); v.z = leaky1(v.z); v.w = leaky1(v.w);
    return v;
}
__device__ __forceinline__ float tf32r(float x) {
    float r; asm("cvt.rna.tf32.f32 %0, %1;" : "=f"(r) : "f"(x)); return r;
}

// -------------------- weight decomposition --------------------
// slot 0: W1, 1: W2[0:256], 2: W2[256:512], 3: Wl[0:256], 4: Wl[256:512]
__global__ void decompose_w(const float* __restrict__ W1, const float* __restrict__ W2,
                            const float* __restrict__ Wl) {
    int slot = blockIdx.y;
    int idx = blockIdx.x * 256 + threadIdx.x;   // 0..65535
    const float* src;
    if (slot == 0) src = W1;
    else if (slot == 1) src = W2;
    else if (slot == 2) src = W2 + 65536;
    else if (slot == 3) src = Wl;
    else src = Wl + 65536;
    float v = src[idx];
    float hi = tf32r(v);
    float lo = tf32r(v - hi);
    WHI[slot * 65536 + idx] = hi;
    WLO[slot * 65536 + idx] = lo;
}

// -------------------- tf32 tensor-core GEMM --------------------
// C[nrows,256] = A[nrows,256] @ B[256,256]  (B given as precomputed hi/lo)
// 3-pass split: Ahi*Bhi + Ahi*Blo + Alo*Bhi. Epilogue: +bias, +rc[batch[row]], leaky.
// Block 256 threads = 8 warps (2 m x 4 n), tile 128x128, BK=16.
#define GAPAD 20   // As row pitch (16 + 4)
#define GBPAD 132  // Bs row pitch (128 + 4)

__device__ __forceinline__ void mma8(float* c, const float* a, const float* b) {
    asm volatile(
        "mma.sync.aligned.m16n8k8.row.col.f32.tf32.tf32.f32 "
        "{%0,%1,%2,%3}, {%4,%5,%6,%7}, {%8,%9}, {%0,%1,%2,%3};"
        : "+f"(c[0]), "+f"(c[1]), "+f"(c[2]), "+f"(c[3])
        : "r"(__float_as_uint(a[0])), "r"(__float_as_uint(a[1])),
          "r"(__float_as_uint(a[2])), "r"(__float_as_uint(a[3])),
          "r"(__float_as_uint(b[0])), "r"(__float_as_uint(b[1])));
}

__global__ void __launch_bounds__(256, 1) gemm_tf32(
    const float* __restrict__ A, const float* __restrict__ BH, const float* __restrict__ BL,
    float* __restrict__ C, const float* __restrict__ bias,
    const float* __restrict__ rc, const int* __restrict__ batch,
    int nrows, int leakyFlag)
{
    __shared__ float As_hi[128 * GAPAD];
    __shared__ float As_lo[128 * GAPAD];
    __shared__ float Bs_hi[16 * GBPAD];
    __shared__ float Bs_lo[16 * GBPAD];

    const int tid = threadIdx.x;
    const int warp = tid >> 5, lane = tid & 31;
    const int g = lane >> 2, t = lane & 3;
    const int wm = (warp & 1) * 64;
    const int wn = (warp >> 1) * 32;
    const int row0 = blockIdx.x * 128;
    const int col0 = blockIdx.y * 128;

    float acc[4][4][4];
    #pragma unroll
    for (int mt = 0; mt < 4; mt++)
        #pragma unroll
        for (int nt = 0; nt < 4; nt++)
            #pragma unroll
            for (int i = 0; i < 4; i++) acc[mt][nt][i] = 0.0f;

    float4 ra[2], rbh[2], rbl[2];

    // prefetch chunk 0
    #pragma unroll
    for (int i = 0; i < 2; i++) {
        int f = tid + 256 * i;
        int r = f >> 2, c4 = (f & 3) * 4;
        int gr = row0 + r;
        ra[i] = (gr < nrows) ? *(const float4*)(A + (long long)gr * 256 + c4)
                             : make_float4(0.f, 0.f, 0.f, 0.f);
        int kr = f >> 5, bc = (f & 31) * 4;
        rbh[i] = *(const float4*)(BH + (long long)kr * 256 + col0 + bc);
        rbl[i] = *(const float4*)(BL + (long long)kr * 256 + col0 + bc);
    }

    for (int ch = 0; ch < 16; ch++) {
        __syncthreads();
        // stage into smem with A hi/lo split
        #pragma unroll
        for (int i = 0; i < 2; i++) {
            int f = tid + 256 * i;
            int r = f >> 2, c4 = (f & 3) * 4;
            float4 v = ra[i];
            float hx = tf32r(v.x), hy = tf32r(v.y), hz = tf32r(v.z), hw = tf32r(v.w);
            As_hi[r * GAPAD + c4 + 0] = hx;
            As_hi[r * GAPAD + c4 + 1] = hy;
            As_hi[r * GAPAD + c4 + 2] = hz;
            As_hi[r * GAPAD + c4 + 3] = hw;
            As_lo[r * GAPAD + c4 + 0] = tf32r(v.x - hx);
            As_lo[r * GAPAD + c4 + 1] = tf32r(v.y - hy);
            As_lo[r * GAPAD + c4 + 2] = tf32r(v.z - hz);
            As_lo[r * GAPAD + c4 + 3] = tf32r(v.w - hw);
            int kr = f >> 5, bc = (f & 31) * 4;
            *(float4*)&Bs_hi[kr * GBPAD + bc] = rbh[i];
            *(float4*)&Bs_lo[kr * GBPAD + bc] = rbl[i];
        }
        __syncthreads();

        // prefetch next chunk
        if (ch < 15) {
            int k0 = (ch + 1) * 16;
            #pragma unroll
            for (int i = 0; i < 2; i++) {
                int f = tid + 256 * i;
                int r = f >> 2, c4 = (f & 3) * 4;
                int gr = row0 + r;
                ra[i] = (gr < nrows) ? *(const float4*)(A + (long long)gr * 256 + k0 + c4)
                                     : make_float4(0.f, 0.f, 0.f, 0.f);
                int kr = f >> 5, bc = (f & 31) * 4;
                rbh[i] = *(const float4*)(BH + (long long)(k0 + kr) * 256 + col0 + bc);
                rbl[i] = *(const float4*)(BL + (long long)(k0 + kr) * 256 + col0 + bc);
            }
        }

        // compute: 2 k8 substeps
        #pragma unroll
        for (int ks = 0; ks < 2; ks++) {
            int kk = ks * 8;
            float ah[4][4], al[4][4];
            #pragma unroll
            for (int mt = 0; mt < 4; mt++) {
                int base = (wm + mt * 16 + g) * GAPAD + kk + t;
                int base8 = base + 8 * GAPAD;
                ah[mt][0] = As_hi[base];     ah[mt][1] = As_hi[base8];
                ah[mt][2] = As_hi[base + 4]; ah[mt][3] = As_hi[base8 + 4];
                al[mt][0] = As_lo[base];     al[mt][1] = As_lo[base8];
                al[mt][2] = As_lo[base + 4]; al[mt][3] = As_lo[base8 + 4];
            }
            float bh[4][2], bl2[4][2];
            #pragma unroll
            for (int nt = 0; nt < 4; nt++) {
                int cb = wn + nt * 8 + g;
                bh[nt][0]  = Bs_hi[(kk + t) * GBPAD + cb];
                bh[nt][1]  = Bs_hi[(kk + t + 4) * GBPAD + cb];
                bl2[nt][0] = Bs_lo[(kk + t) * GBPAD + cb];
                bl2[nt][1] = Bs_lo[(kk + t + 4) * GBPAD + cb];
            }
            #pragma unroll
            for (int mt = 0; mt < 4; mt++)
                #pragma unroll
                for (int nt = 0; nt < 4; nt++) {
                    mma8(acc[mt][nt], ah[mt], bh[nt]);
                    mma8(acc[mt][nt], ah[mt], bl2[nt]);
                    mma8(acc[mt][nt], al[mt], bh[nt]);
                }
        }
    }

    // epilogue
    #pragma unroll
    for (int mt = 0; mt < 4; mt++) {
        int r_lo = row0 + wm + mt * 16 + g;
        #pragma unroll
        for (int h = 0; h < 2; h++) {
            int gr = r_lo + 8 * h;
            if (gr >= nrows) continue;
            const float* rcrow = rc ? rc + (long long)batch[gr] * 256 : nullptr;
            #pragma unroll
            for (int nt = 0; nt < 4; nt++) {
                int gc = col0 + wn + nt * 8 + 2 * t;
                float vx = acc[mt][nt][h * 2 + 0];
                float vy = acc[mt][nt][h * 2 + 1];
                if (bias) { float2 bb = *(const float2*)(bias + gc); vx += bb.x; vy += bb.y; }
                if (rcrow) { float2 rr = *(const float2*)(rcrow + gc); vx += rr.x; vy += rr.y; }
                if (leakyFlag) { vx = leaky1(vx); vy = leaky1(vy); }
                float2 o; o.x = vx; o.y = vy;
                *(float2*)(C + (long long)gr * 256 + gc) = o;
            }
        }
    }
}

// -------------------- edge scatter: agg[dst] += w * h[src] --------------------
__global__ void __launch_bounds__(256) scatter_kernel(
    const float* __restrict__ h, float* __restrict__ agg,
    const int* __restrict__ src, const int* __restrict__ dst,
    const float* __restrict__ w, int E)
{
    int warp = (blockIdx.x * blockDim.x + threadIdx.x) >> 5;
    int lane = threadIdx.x & 31;
    if (warp >= E) return;
    int s = src[warp], d = dst[warp];
    float wt = w[warp];
    const float4* hrow = (const float4*)(h + (long long)s * DIM);
    float* arow = agg + (long long)d * DIM;
    #pragma unroll
    for (int i = 0; i < 2; i++) {
        int gidx = lane + 32 * i;
        float4 v = __ldg(hrow + gidx);
        float* p = arow + gidx * 4;
#if __CUDA_ARCH__ >= 900
        asm volatile("red.global.add.v4.f32 [%0], {%1,%2,%3,%4};"
                     :: "l"(p), "f"(wt * v.x), "f"(wt * v.y), "f"(wt * v.z), "f"(wt * v.w)
                     : "memory");
#else
        atomicAdd(p + 0, wt * v.x); atomicAdd(p + 1, wt * v.y);
        atomicAdd(p + 2, wt * v.z); atomicAdd(p + 3, wt * v.w);
#endif
    }
}

// -------------------- small helpers --------------------
__global__ void zero_kernel(float4* __restrict__ p, long long n4) {
    long long i = (long long)blockIdx.x * blockDim.x + threadIdx.x;
    if (i < n4) p[i] = make_float4(0.f, 0.f, 0.f, 0.f);
}

// dst[b] = (leaky?) src[root_idx[b]]
__global__ void __launch_bounds__(64) gather_root(
    const float* __restrict__ src, const int* __restrict__ root_idx,
    float* __restrict__ dst, int applyLeaky)
{
    int b = blockIdx.x, t = threadIdx.x;
    int r = root_idx[b];
    float4 v = ((const float4*)(src + (long long)r * DIM))[t];
    if (applyLeaky) v = leaky4(v);
    ((float4*)(dst + (long long)b * DIM))[t] = v;
}

// out_raw (optional) = in + bias ; out_leaky = leaky(in + bias)
__global__ void __launch_bounds__(64) addbias_kernel(
    const float* __restrict__ in, const float* __restrict__ bias,
    float* __restrict__ out_raw, float* __restrict__ out_leaky, int N)
{
    int i = blockIdx.x, t = threadIdx.x;
    if (i >= N) return;
    float4 v = ((const float4*)(in + (long long)i * DIM))[t];
    float4 bb = ((const float4*)bias)[t];
    v.x += bb.x; v.y += bb.y; v.z += bb.z; v.w += bb.w;
    if (out_raw) ((float4*)(out_raw + (long long)i * DIM))[t] = v;
    ((float4*)(out_leaky + (long long)i * DIM))[t] = leaky4(v);
}

// -------------------- launch --------------------
extern "C" void kernel_launch(void* const* d_in, const int* in_sizes, int n_in,
                              void* d_out, int out_size)
{
    const float* features = (const float*)d_in[0];
    const float* values   = (const float*)d_in[1];
    const float* W1       = (const float*)d_in[2];
    const float* b1       = (const float*)d_in[3];
    const float* W2       = (const float*)d_in[4];
    const float* b2       = (const float*)d_in[5];
    const float* Wl       = (const float*)d_in[6];
    const float* bl       = (const float*)d_in[7];
    const int*   adjs     = (const int*)d_in[8];
    const int*   batch    = (const int*)d_in[9];
    const int*   root_idx = (const int*)d_in[10];
    float* out = (float*)d_out;

    const int N = in_sizes[0] / DIM;
    const int E = in_sizes[1];
    const int B = in_sizes[10];
    const int* src = adjs;
    const int* dst = adjs + E;

    float *bufA, *bufB, *bufC, *whi, *wlo, *ra2, *ra3, *rc2, *rc3;
    cudaGetSymbolAddress((void**)&bufA, BUF_A);
    cudaGetSymbolAddress((void**)&bufB, BUF_B);
    cudaGetSymbolAddress((void**)&bufC, BUF_C);
    cudaGetSymbolAddress((void**)&whi, WHI);
    cudaGetSymbolAddress((void**)&wlo, WLO);
    cudaGetSymbolAddress((void**)&ra2, RA2);
    cudaGetSymbolAddress((void**)&ra3, RA3);
    cudaGetSymbolAddress((void**)&rc2, RC2);
    cudaGetSymbolAddress((void**)&rc3, RC3);

    dim3 gemmGrid((N + 127) / 128, 2);
    dim3 tinyGrid((B + 127) / 128, 2);
    int scatterBlocks = (E + 7) / 8;
    long long n4 = (long long)N * DIM / 4;
    int zeroBlocks = (int)((n4 + 255) / 256);

    // 1. decompose weights into tf32 hi/lo
    decompose_w<<<dim3(256, 5), 256>>>(W1, W2, Wl);
    // 2. rootA2 = leaky(features[root]); rc2 = rootA2 @ W2bot
    gather_root<<<B, 64>>>(features, root_idx, ra2, 1);
    gemm_tf32<<<tinyGrid, 256>>>(ra2, whi + 2 * 65536, wlo + 2 * 65536, rc2,
                                 nullptr, nullptr, nullptr, B, 0);
    // 3. zero agg1
    zero_kernel<<<zeroBlocks, 256>>>((float4*)bufC, n4);
    // 4. h_lin = features @ W1
    gemm_tf32<<<gemmGrid, 256>>>(features, whi, wlo, bufB,
                                 nullptr, nullptr, nullptr, N, 0);
    // 5. agg1[dst] += v * h_lin[src]
    scatter_kernel<<<scatterBlocks, 256>>>(bufB, bufC, src, dst, values, E);
    // 6. h1 = agg1 + b1 (in place); A2 = leaky(h1)
    addbias_kernel<<<N, 64>>>(bufC, b1, bufC, bufA, N);
    // 7. rootA3 = h1[root]; rc3 = rootA3 @ Wlbot
    gather_root<<<B, 64>>>(bufC, root_idx, ra3, 0);
    gemm_tf32<<<tinyGrid, 256>>>(ra3, whi + 4 * 65536, wlo + 4 * 65536, rc3,
                                 nullptr, nullptr, nullptr, B, 0);
    // 8. zero agg2
    zero_kernel<<<zeroBlocks, 256>>>((float4*)bufC, n4);
    // 9. h2_lin = A2 @ W2top + rc2[batch]
    gemm_tf32<<<gemmGrid, 256>>>(bufA, whi + 1 * 65536, wlo + 1 * 65536, bufB,
                                 nullptr, rc2, batch, N, 0);
    // 10. agg2[dst] += v * h2_lin[src]
    scatter_kernel<<<scatterBlocks, 256>>>(bufB, bufC, src, dst, values, E);
    // 11. A3 = leaky(agg2 + b2)
    addbias_kernel<<<N, 64>>>(bufC, b2, nullptr, bufA, N);
    // 12. out = leaky(A3 @ Wltop + rc3[batch] + bl)
    gemm_tf32<<<gemmGrid, 256>>>(bufA, whi + 3 * 65536, wlo + 3 * 65536, out,
                                 bl, rc3, batch, N, 1);
}